// round 1
// baseline (speedup 1.0000x reference)
#include <cuda_runtime.h>
#include <math.h>

// Problem dims (fixed)
#define BB   16
#define LL   2048
#define HH   256
#define NN   64
#define NLAY 4
#define IND  40
#define OUTD 33

typedef unsigned long long ull;

// ------------------------------------------------------------------
// Scratch (device globals: allocation-free per harness rules)
// ------------------------------------------------------------------
__device__ float g_h[BB * LL * HH];   // residual stream
__device__ float g_z[BB * LL * HH];   // layernorm output
__device__ float g_y[BB * LL * HH];   // SSM output / gelu output
__device__ float g_ar[HH * NN];       // Re(dA)
__device__ float g_ai[HH * NN];       // Im(dA)
__device__ float g_wr[HH * NN];       // 2*Re(C*dB)
__device__ float g_win[HH * NN];      // -2*Im(C*dB)

// ------------------------------------------------------------------
// f32x2 packed math (Blackwell)
// ------------------------------------------------------------------
__device__ __forceinline__ ull pk2(float lo, float hi) {
    ull r;
    asm("mov.b64 %0, {%1, %2};" : "=l"(r) : "f"(lo), "f"(hi));
    return r;
}
__device__ __forceinline__ void upk2(ull v, float& lo, float& hi) {
    asm("mov.b64 {%0, %1}, %2;" : "=f"(lo), "=f"(hi) : "l"(v));
}
__device__ __forceinline__ ull fma2(ull a, ull b, ull c) {
    ull d;
    asm("fma.rn.f32x2 %0, %1, %2, %3;" : "=l"(d) : "l"(a), "l"(b), "l"(c));
    return d;
}
__device__ __forceinline__ ull mul2(ull a, ull b) {
    ull d;
    asm("mul.rn.f32x2 %0, %1, %2;" : "=l"(d) : "l"(a), "l"(b));
    return d;
}

// ------------------------------------------------------------------
// Encoder: h[m, :] = enc_w @ x[m, :] + enc_b     (M = B*L, K = 40)
// 16 rows per block; enc_w cached transposed in smem.
// ------------------------------------------------------------------
__global__ void enc_kernel(const float* __restrict__ x,
                           const float* __restrict__ ew,
                           const float* __restrict__ eb) {
    __shared__ float sw[IND * HH];   // sw[i*256 + h] = ew[h*40 + i]
    __shared__ float sx[16 * IND];
    int tid = threadIdx.x;
    for (int idx = tid; idx < HH * IND; idx += 256) {
        int h = idx / IND, i = idx % IND;
        sw[i * HH + h] = ew[idx];
    }
    int m0 = blockIdx.x * 16;
    for (int idx = tid; idx < 16 * IND; idx += 256)
        sx[idx] = x[(size_t)m0 * IND + idx];
    __syncthreads();
    float bias = eb[tid];
    for (int r = 0; r < 16; ++r) {
        float acc = bias;
        #pragma unroll
        for (int i = 0; i < IND; ++i)
            acc = fmaf(sx[r * IND + i], sw[i * HH + tid], acc);
        g_h[(size_t)(m0 + r) * HH + tid] = acc;
    }
}

// ------------------------------------------------------------------
// LayerNorm over H=256: one warp per row, 8 elems/lane (2x float4)
// ------------------------------------------------------------------
__global__ void ln_kernel(const float* __restrict__ sc,
                          const float* __restrict__ bi) {
    int warp = (blockIdx.x * blockDim.x + threadIdx.x) >> 5;   // row
    int lane = threadIdx.x & 31;
    const float* row = g_h + (size_t)warp * HH;
    float4 v0 = *reinterpret_cast<const float4*>(row + lane * 4);
    float4 v1 = *reinterpret_cast<const float4*>(row + 128 + lane * 4);
    float s = v0.x + v0.y + v0.z + v0.w + v1.x + v1.y + v1.z + v1.w;
    float q = v0.x*v0.x + v0.y*v0.y + v0.z*v0.z + v0.w*v0.w
            + v1.x*v1.x + v1.y*v1.y + v1.z*v1.z + v1.w*v1.w;
    #pragma unroll
    for (int m = 16; m; m >>= 1) {
        s += __shfl_xor_sync(0xffffffffu, s, m);
        q += __shfl_xor_sync(0xffffffffu, q, m);
    }
    float mu  = s * (1.0f / 256.0f);
    float var = q * (1.0f / 256.0f) - mu * mu;
    float inv = rsqrtf(var + 1e-5f);
    float* zr = g_z + (size_t)warp * HH;
    int h0 = lane * 4;
    float4 o0, o1;
    o0.x = (v0.x - mu) * inv * sc[h0+0] + bi[h0+0];
    o0.y = (v0.y - mu) * inv * sc[h0+1] + bi[h0+1];
    o0.z = (v0.z - mu) * inv * sc[h0+2] + bi[h0+2];
    o0.w = (v0.w - mu) * inv * sc[h0+3] + bi[h0+3];
    int h1 = 128 + lane * 4;
    o1.x = (v1.x - mu) * inv * sc[h1+0] + bi[h1+0];
    o1.y = (v1.y - mu) * inv * sc[h1+1] + bi[h1+1];
    o1.z = (v1.z - mu) * inv * sc[h1+2] + bi[h1+2];
    o1.w = (v1.w - mu) * inv * sc[h1+3] + bi[h1+3];
    *reinterpret_cast<float4*>(zr + h0) = o0;
    *reinterpret_cast<float4*>(zr + h1) = o1;
}

// ------------------------------------------------------------------
// S4D discretization: dA = exp(lam*dt), w = 2 * C * (dA-1)/lam
// ------------------------------------------------------------------
__global__ void ssm_params_kernel(const float* __restrict__ lre,
                                  const float* __restrict__ lim,
                                  const float* __restrict__ cre,
                                  const float* __restrict__ cim,
                                  const float* __restrict__ lstep) {
    int idx = blockIdx.x * blockDim.x + threadIdx.x;   // h*64 + n
    if (idx >= HH * NN) return;
    int h = idx >> 6;
    float Lre = lre[idx], Lim = lim[idx];
    float Cre = cre[idx], Cim = cim[idx];
    float dt  = expf(lstep[h]);
    float mag = expf(Lre * dt);
    float th  = Lim * dt;
    float dar = mag * cosf(th);
    float dai = mag * sinf(th);
    float den = Lre * Lre + Lim * Lim;
    float nr = dar - 1.0f, ni = dai;
    float dbr = (nr * Lre + ni * Lim) / den;
    float dbi = (ni * Lre - nr * Lim) / den;
    float wr = Cre * dbr - Cim * dbi;
    float wi = Cre * dbi + Cim * dbr;
    g_ar[idx]  = dar;
    g_ai[idx]  = dai;
    g_wr[idx]  = 2.0f * wr;
    g_win[idx] = -2.0f * wi;
}

// ------------------------------------------------------------------
// SSM scan: y[l] = 2Re(sum_n w_n s_n[l]) + d*z[l],  s = dA*s + z.
// 2 sequences per warp; 16 lanes/seq; 4 complex states per lane,
// packed as f32x2 pairs. Reduction via 4x shfl_xor within 16 lanes.
// ------------------------------------------------------------------
__global__ void scan_kernel(const float* __restrict__ dcoef) {
    int warp = (blockIdx.x * blockDim.x + threadIdx.x) >> 5;   // 0..2047
    int lane = threadIdx.x & 31;
    int half = lane >> 4;
    int ln   = lane & 15;
    int seq  = warp * 2 + half;        // b*H + h
    int b = seq >> 8;
    int h = seq & 255;
    int base = h * NN + ln * 4;

    float a0r = g_ar[base+0], a1r = g_ar[base+1], a2r = g_ar[base+2], a3r = g_ar[base+3];
    float a0i = g_ai[base+0], a1i = g_ai[base+1], a2i = g_ai[base+2], a3i = g_ai[base+3];
    float w0r = g_wr[base+0], w1r = g_wr[base+1], w2r = g_wr[base+2], w3r = g_wr[base+3];
    float w0n = g_win[base+0], w1n = g_win[base+1], w2n = g_win[base+2], w3n = g_win[base+3];

    ull ar01 = pk2(a0r, a1r), ar23 = pk2(a2r, a3r);
    ull ai01 = pk2(a0i, a1i), ai23 = pk2(a2i, a3i);
    ull an01 = pk2(-a0i, -a1i), an23 = pk2(-a2i, -a3i);
    ull wr01 = pk2(w0r, w1r), wr23 = pk2(w2r, w3r);
    ull wn01 = pk2(w0n, w1n), wn23 = pk2(w2n, w3n);

    ull sr01 = 0ULL, si01 = 0ULL, sr23 = 0ULL, si23 = 0ULL;

    const float* zp = g_z + ((size_t)b * LL) * HH + h;
    float*       yp = g_y + ((size_t)b * LL) * HH + h;
    float dv = dcoef[h];

    #pragma unroll 4
    for (int l = 0; l < LL; ++l) {
        float zv = __ldg(zp + (size_t)l * HH);
        ull z2 = pk2(zv, zv);
        // pair 0/1
        ull t0 = fma2(an01, si01, z2);            // -ai*si + z   (old si)
        si01   = fma2(ai01, sr01, mul2(ar01, si01)); // ai*sr_old + ar*si_old
        sr01   = fma2(ar01, sr01, t0);            // ar*sr_old - ai*si_old + z
        // pair 2/3
        ull t1 = fma2(an23, si23, z2);
        si23   = fma2(ai23, sr23, mul2(ar23, si23));
        sr23   = fma2(ar23, sr23, t1);
        // output contribution: 2*(wr*sr - wi*si)
        ull av = fma2(wr01, sr01, mul2(wn01, si01));
        av = fma2(wr23, sr23, av);
        av = fma2(wn23, si23, av);
        float alo, ahi;
        upk2(av, alo, ahi);
        float acc = alo + ahi;
        acc += __shfl_xor_sync(0xffffffffu, acc, 1);
        acc += __shfl_xor_sync(0xffffffffu, acc, 2);
        acc += __shfl_xor_sync(0xffffffffu, acc, 4);
        acc += __shfl_xor_sync(0xffffffffu, acc, 8);
        float yv = fmaf(dv, zv, acc);
        if (ln == 0) yp[(size_t)l * HH] = yv;
    }
}

// ------------------------------------------------------------------
// gelu (tanh approx, matching jax.nn.gelu approximate=True), in place
// ------------------------------------------------------------------
__global__ void gelu_kernel() {
    const float c0 = 0.7978845608028654f;   // sqrt(2/pi)
    const float c1 = 0.044715f;
    int n4 = (BB * LL * HH) / 4;
    for (int i = blockIdx.x * blockDim.x + threadIdx.x; i < n4;
         i += gridDim.x * blockDim.x) {
        float4 v = reinterpret_cast<float4*>(g_y)[i];
        float r[4] = {v.x, v.y, v.z, v.w};
        #pragma unroll
        for (int j = 0; j < 4; ++j) {
            float xv = r[j];
            float t = tanhf(c0 * (xv + c1 * xv * xv * xv));
            r[j] = 0.5f * xv * (1.0f + t);
        }
        reinterpret_cast<float4*>(g_y)[i] = make_float4(r[0], r[1], r[2], r[3]);
    }
}

// ------------------------------------------------------------------
// Fused GLU GEMM: g1 = Y@W1^T + b1, g2 = Y@W2^T + b2,
// h = h + g1 * sigmoid(g2).  M=32768, N=256, K=256.
// 64x64 tile, BK=16, 256 threads, 4x4 microtile, f32x2 accumulators.
// ------------------------------------------------------------------
#define GBM 64
#define GBN 64
#define GBK 16
__global__ void glu_gemm_kernel(const float* __restrict__ W1,
                                const float* __restrict__ W2,
                                const float* __restrict__ b1,
                                const float* __restrict__ b2) {
    __shared__ float As [GBK][68];
    __shared__ float Bs1[GBK][68];
    __shared__ float Bs2[GBK][68];
    int tid = threadIdx.x;
    int m0 = blockIdx.x * GBM;
    int n0 = blockIdx.y * GBN;
    int ty = tid >> 4, tx = tid & 15;
    int lm = tid >> 2;                  // 0..63
    int lk = (tid & 3) << 2;            // 0,4,8,12

    ull acc1[4][2], acc2[4][2];
    #pragma unroll
    for (int i = 0; i < 4; ++i)
        for (int p = 0; p < 2; ++p) { acc1[i][p] = 0ULL; acc2[i][p] = 0ULL; }

    for (int kt = 0; kt < HH / GBK; ++kt) {
        int k0 = kt * GBK;
        float4 av = *reinterpret_cast<const float4*>(
            &g_y[(size_t)(m0 + lm) * HH + k0 + lk]);
        float4 w1v = *reinterpret_cast<const float4*>(
            &W1[(size_t)(n0 + lm) * HH + k0 + lk]);
        float4 w2v = *reinterpret_cast<const float4*>(
            &W2[(size_t)(n0 + lm) * HH + k0 + lk]);
        __syncthreads();
        As [lk+0][lm] = av.x;  As [lk+1][lm] = av.y;
        As [lk+2][lm] = av.z;  As [lk+3][lm] = av.w;
        Bs1[lk+0][lm] = w1v.x; Bs1[lk+1][lm] = w1v.y;
        Bs1[lk+2][lm] = w1v.z; Bs1[lk+3][lm] = w1v.w;
        Bs2[lk+0][lm] = w2v.x; Bs2[lk+1][lm] = w2v.y;
        Bs2[lk+2][lm] = w2v.z; Bs2[lk+3][lm] = w2v.w;
        __syncthreads();
        #pragma unroll
        for (int k = 0; k < GBK; ++k) {
            float4 a   = *reinterpret_cast<const float4*>(&As [k][ty * 4]);
            float4 bv1 = *reinterpret_cast<const float4*>(&Bs1[k][tx * 4]);
            float4 bv2 = *reinterpret_cast<const float4*>(&Bs2[k][tx * 4]);
            ull b1p0 = pk2(bv1.x, bv1.y), b1p1 = pk2(bv1.z, bv1.w);
            ull b2p0 = pk2(bv2.x, bv2.y), b2p1 = pk2(bv2.z, bv2.w);
            float avr[4] = {a.x, a.y, a.z, a.w};
            #pragma unroll
            for (int i = 0; i < 4; ++i) {
                ull aa = pk2(avr[i], avr[i]);
                acc1[i][0] = fma2(aa, b1p0, acc1[i][0]);
                acc1[i][1] = fma2(aa, b1p1, acc1[i][1]);
                acc2[i][0] = fma2(aa, b2p0, acc2[i][0]);
                acc2[i][1] = fma2(aa, b2p1, acc2[i][1]);
            }
        }
    }

    float bb1[4], bb2[4];
    #pragma unroll
    for (int j = 0; j < 4; ++j) {
        bb1[j] = b1[n0 + tx * 4 + j];
        bb2[j] = b2[n0 + tx * 4 + j];
    }
    #pragma unroll
    for (int i = 0; i < 4; ++i) {
        int row = m0 + ty * 4 + i;
        float* hp = &g_h[(size_t)row * HH + n0 + tx * 4];
        float4 hv = *reinterpret_cast<float4*>(hp);
        float g1v[4], g2v[4];
        upk2(acc1[i][0], g1v[0], g1v[1]); upk2(acc1[i][1], g1v[2], g1v[3]);
        upk2(acc2[i][0], g2v[0], g2v[1]); upk2(acc2[i][1], g2v[2], g2v[3]);
        float hvv[4] = {hv.x, hv.y, hv.z, hv.w};
        float o[4];
        #pragma unroll
        for (int j = 0; j < 4; ++j) {
            float gate = g2v[j] + bb2[j];
            float sig  = 1.0f / (1.0f + expf(-gate));
            o[j] = hvv[j] + (g1v[j] + bb1[j]) * sig;
        }
        *reinterpret_cast<float4*>(hp) = make_float4(o[0], o[1], o[2], o[3]);
    }
}

// ------------------------------------------------------------------
// Decoder: out[m, o] = sum_h h[m,h]*dec_w[o,h] + dec_b[o]; warp/row
// ------------------------------------------------------------------
__global__ void dec_kernel(const float* __restrict__ dw,
                           const float* __restrict__ db,
                           float* __restrict__ out) {
    int warp = (blockIdx.x * blockDim.x + threadIdx.x) >> 5;   // row
    int lane = threadIdx.x & 31;
    const float* row = g_h + (size_t)warp * HH;
    float hr[8];
    #pragma unroll
    for (int k = 0; k < 8; ++k) hr[k] = row[lane + 32 * k];
    for (int o = 0; o < OUTD; ++o) {
        const float* wrow = dw + o * HH + lane;
        float acc = 0.0f;
        #pragma unroll
        for (int k = 0; k < 8; ++k) acc = fmaf(hr[k], wrow[32 * k], acc);
        #pragma unroll
        for (int m = 16; m; m >>= 1) acc += __shfl_xor_sync(0xffffffffu, acc, m);
        if (lane == 0) out[(size_t)warp * OUTD + o] = acc + db[o];
    }
}

// ------------------------------------------------------------------
extern "C" void kernel_launch(void* const* d_in, const int* in_sizes, int n_in,
                              void* d_out, int out_size) {
    const float* x     = (const float*)d_in[0];
    const float* enc_w = (const float*)d_in[1];
    const float* enc_b = (const float*)d_in[2];
    const float* lre   = (const float*)d_in[3];
    const float* lim   = (const float*)d_in[4];
    const float* cre   = (const float*)d_in[5];
    const float* cim   = (const float*)d_in[6];
    const float* dd    = (const float*)d_in[7];
    const float* lstep = (const float*)d_in[8];
    const float* lns   = (const float*)d_in[9];
    const float* lnb   = (const float*)d_in[10];
    const float* ow    = (const float*)d_in[11];
    const float* ob    = (const float*)d_in[12];
    const float* o2w   = (const float*)d_in[13];
    const float* o2b   = (const float*)d_in[14];
    const float* dw    = (const float*)d_in[15];
    const float* db    = (const float*)d_in[16];
    float* out = (float*)d_out;

    enc_kernel<<<(BB * LL) / 16, 256>>>(x, enc_w, enc_b);

    for (int li = 0; li < NLAY; ++li) {
        ln_kernel<<<(BB * LL) / 8, 256>>>(lns + li * HH, lnb + li * HH);
        ssm_params_kernel<<<(HH * NN) / 256, 256>>>(
            lre + li * HH * NN, lim + li * HH * NN,
            cre + li * HH * NN, cim + li * HH * NN, lstep + li * HH);
        scan_kernel<<<(BB * HH) / (2 * 8), 256>>>(dd + li * HH);
        gelu_kernel<<<1024, 256>>>();
        glu_gemm_kernel<<<dim3((BB * LL) / GBM, HH / GBN), 256>>>(
            ow + li * HH * HH, o2w + li * HH * HH,
            ob + li * HH, o2b + li * HH);
    }

    dec_kernel<<<(BB * LL) / 8, 256>>>(dw, db, out);
}

// round 2
// speedup vs baseline: 1.3026x; 1.3026x over previous
#include <cuda_runtime.h>
#include <math.h>

// Problem dims (fixed)
#define BB   16
#define LL   2048
#define HH   256
#define NN   64
#define NLAY 4
#define IND  40
#define OUTD 33

// Chunked-scan config
#define CH    4
#define CLEN  512   // LL / CH

typedef unsigned long long ull;

// ------------------------------------------------------------------
// Scratch (device globals: allocation-free per harness rules)
// ------------------------------------------------------------------
__device__ float g_h[BB * LL * HH];   // residual stream
__device__ float g_z[BB * LL * HH];   // layernorm output
__device__ float g_y[BB * LL * HH];   // SSM output / gelu output
__device__ float g_ar[HH * NN];       // Re(dA)
__device__ float g_ai[HH * NN];       // Im(dA)
__device__ float g_wr[HH * NN];       // 2*Re(C*dB)
__device__ float g_win[HH * NN];      // -2*Im(C*dB)
__device__ float g_apr[HH * NN];      // Re(dA^CLEN)
__device__ float g_api[HH * NN];      // Im(dA^CLEN)
// chunk end / init states: [seq*CH + c][n]  (seq = b*H + h, n in 0..63)
__device__ float g_esr[BB * HH * CH * NN];
__device__ float g_esi[BB * HH * CH * NN];
__device__ float g_isr[BB * HH * CH * NN];
__device__ float g_isi[BB * HH * CH * NN];

// ------------------------------------------------------------------
// f32x2 packed math (Blackwell)
// ------------------------------------------------------------------
__device__ __forceinline__ ull pk2(float lo, float hi) {
    ull r;
    asm("mov.b64 %0, {%1, %2};" : "=l"(r) : "f"(lo), "f"(hi));
    return r;
}
__device__ __forceinline__ void upk2(ull v, float& lo, float& hi) {
    asm("mov.b64 {%0, %1}, %2;" : "=f"(lo), "=f"(hi) : "l"(v));
}
__device__ __forceinline__ ull fma2(ull a, ull b, ull c) {
    ull d;
    asm("fma.rn.f32x2 %0, %1, %2, %3;" : "=l"(d) : "l"(a), "l"(b), "l"(c));
    return d;
}
__device__ __forceinline__ ull mul2(ull a, ull b) {
    ull d;
    asm("mul.rn.f32x2 %0, %1, %2;" : "=l"(d) : "l"(a), "l"(b));
    return d;
}
__device__ __forceinline__ ull add2(ull a, ull b) {
    ull d;
    asm("add.rn.f32x2 %0, %1, %2;" : "=l"(d) : "l"(a), "l"(b));
    return d;
}

// ------------------------------------------------------------------
// Encoder: h[m, :] = enc_w @ x[m, :] + enc_b     (M = B*L, K = 40)
// ------------------------------------------------------------------
__global__ void enc_kernel(const float* __restrict__ x,
                           const float* __restrict__ ew,
                           const float* __restrict__ eb) {
    __shared__ float sw[IND * HH];
    __shared__ float sx[16 * IND];
    int tid = threadIdx.x;
    for (int idx = tid; idx < HH * IND; idx += 256) {
        int h = idx / IND, i = idx % IND;
        sw[i * HH + h] = ew[idx];
    }
    int m0 = blockIdx.x * 16;
    for (int idx = tid; idx < 16 * IND; idx += 256)
        sx[idx] = x[(size_t)m0 * IND + idx];
    __syncthreads();
    float bias = eb[tid];
    for (int r = 0; r < 16; ++r) {
        float acc = bias;
        #pragma unroll
        for (int i = 0; i < IND; ++i)
            acc = fmaf(sx[r * IND + i], sw[i * HH + tid], acc);
        g_h[(size_t)(m0 + r) * HH + tid] = acc;
    }
}

// ------------------------------------------------------------------
// LayerNorm over H=256: one warp per row
// ------------------------------------------------------------------
__global__ void ln_kernel(const float* __restrict__ sc,
                          const float* __restrict__ bi) {
    int warp = (blockIdx.x * blockDim.x + threadIdx.x) >> 5;
    int lane = threadIdx.x & 31;
    const float* row = g_h + (size_t)warp * HH;
    float4 v0 = *reinterpret_cast<const float4*>(row + lane * 4);
    float4 v1 = *reinterpret_cast<const float4*>(row + 128 + lane * 4);
    float s = v0.x + v0.y + v0.z + v0.w + v1.x + v1.y + v1.z + v1.w;
    float q = v0.x*v0.x + v0.y*v0.y + v0.z*v0.z + v0.w*v0.w
            + v1.x*v1.x + v1.y*v1.y + v1.z*v1.z + v1.w*v1.w;
    #pragma unroll
    for (int m = 16; m; m >>= 1) {
        s += __shfl_xor_sync(0xffffffffu, s, m);
        q += __shfl_xor_sync(0xffffffffu, q, m);
    }
    float mu  = s * (1.0f / 256.0f);
    float var = q * (1.0f / 256.0f) - mu * mu;
    float inv = rsqrtf(var + 1e-5f);
    float* zr = g_z + (size_t)warp * HH;
    int h0 = lane * 4;
    float4 o0, o1;
    o0.x = (v0.x - mu) * inv * sc[h0+0] + bi[h0+0];
    o0.y = (v0.y - mu) * inv * sc[h0+1] + bi[h0+1];
    o0.z = (v0.z - mu) * inv * sc[h0+2] + bi[h0+2];
    o0.w = (v0.w - mu) * inv * sc[h0+3] + bi[h0+3];
    int h1 = 128 + lane * 4;
    o1.x = (v1.x - mu) * inv * sc[h1+0] + bi[h1+0];
    o1.y = (v1.y - mu) * inv * sc[h1+1] + bi[h1+1];
    o1.z = (v1.z - mu) * inv * sc[h1+2] + bi[h1+2];
    o1.w = (v1.w - mu) * inv * sc[h1+3] + bi[h1+3];
    *reinterpret_cast<float4*>(zr + h0) = o0;
    *reinterpret_cast<float4*>(zr + h1) = o1;
}

// ------------------------------------------------------------------
// S4D discretization: dA = exp(lam*dt), w = 2 * C * (dA-1)/lam,
// plus dA^CLEN (double precision) for the chunk combine.
// ------------------------------------------------------------------
__global__ void ssm_params_kernel(const float* __restrict__ lre,
                                  const float* __restrict__ lim,
                                  const float* __restrict__ cre,
                                  const float* __restrict__ cim,
                                  const float* __restrict__ lstep) {
    int idx = blockIdx.x * blockDim.x + threadIdx.x;
    if (idx >= HH * NN) return;
    int h = idx >> 6;
    float Lre = lre[idx], Lim = lim[idx];
    float Cre = cre[idx], Cim = cim[idx];
    float dt  = expf(lstep[h]);
    float mag = expf(Lre * dt);
    float th  = Lim * dt;
    float dar = mag * cosf(th);
    float dai = mag * sinf(th);
    float den = Lre * Lre + Lim * Lim;
    float nr = dar - 1.0f, ni = dai;
    float dbr = (nr * Lre + ni * Lim) / den;
    float dbi = (ni * Lre - nr * Lim) / den;
    float wr = Cre * dbr - Cim * dbi;
    float wi = Cre * dbi + Cim * dbr;
    g_ar[idx]  = dar;
    g_ai[idx]  = dai;
    g_wr[idx]  = 2.0f * wr;
    g_win[idx] = -2.0f * wi;
    // dA^CLEN in double
    double dtd = exp((double)lstep[h]);
    double mr  = exp((double)Lre * dtd * (double)CLEN);
    double thd = (double)Lim * dtd * (double)CLEN;
    g_apr[idx] = (float)(mr * cos(thd));
    g_api[idx] = (float)(mr * sin(thd));
}

// ------------------------------------------------------------------
// Scan pass 1: per (seq, chunk), local scan with s0 = 0.
// 2 units/warp; 16 lanes/unit; 4 complex states/lane (f32x2 pairs).
// Writes partial y (incl. d*z) and the chunk-final state.
// ------------------------------------------------------------------
__global__ void scan1_kernel(const float* __restrict__ dcoef) {
    int warp = (blockIdx.x * blockDim.x + threadIdx.x) >> 5;
    int lane = threadIdx.x & 31;
    int half = lane >> 4;
    int ln   = lane & 15;
    int unit = warp * 2 + half;        // 0..B*H*CH-1
    int seq  = unit >> 2;              // unit / CH
    int c    = unit & (CH - 1);
    int b = seq >> 8;
    int h = seq & 255;
    int base = h * NN + ln * 4;

    float a0r = g_ar[base+0], a1r = g_ar[base+1], a2r = g_ar[base+2], a3r = g_ar[base+3];
    float a0i = g_ai[base+0], a1i = g_ai[base+1], a2i = g_ai[base+2], a3i = g_ai[base+3];
    float w0r = g_wr[base+0], w1r = g_wr[base+1], w2r = g_wr[base+2], w3r = g_wr[base+3];
    float w0n = g_win[base+0], w1n = g_win[base+1], w2n = g_win[base+2], w3n = g_win[base+3];

    ull ar01 = pk2(a0r, a1r), ar23 = pk2(a2r, a3r);
    ull ai01 = pk2(a0i, a1i), ai23 = pk2(a2i, a3i);
    ull an01 = pk2(-a0i, -a1i), an23 = pk2(-a2i, -a3i);
    ull wr01 = pk2(w0r, w1r), wr23 = pk2(w2r, w3r);
    ull wn01 = pk2(w0n, w1n), wn23 = pk2(w2n, w3n);

    ull sr01 = 0ULL, si01 = 0ULL, sr23 = 0ULL, si23 = 0ULL;

    const float* zp = g_z + ((size_t)b * LL + (size_t)c * CLEN) * HH + h;
    float*       yp = g_y + ((size_t)b * LL + (size_t)c * CLEN) * HH + h;
    float dv = dcoef[h];

    #pragma unroll 4
    for (int l = 0; l < CLEN; ++l) {
        float zv = __ldg(zp + (size_t)l * HH);
        ull z2 = pk2(zv, zv);
        ull t0 = fma2(an01, si01, z2);
        si01   = fma2(ai01, sr01, mul2(ar01, si01));
        sr01   = fma2(ar01, sr01, t0);
        ull t1 = fma2(an23, si23, z2);
        si23   = fma2(ai23, sr23, mul2(ar23, si23));
        sr23   = fma2(ar23, sr23, t1);
        ull av = fma2(wr01, sr01, mul2(wn01, si01));
        av = fma2(wr23, sr23, av);
        av = fma2(wn23, si23, av);
        float alo, ahi;
        upk2(av, alo, ahi);
        float acc = alo + ahi;
        acc += __shfl_xor_sync(0xffffffffu, acc, 1);
        acc += __shfl_xor_sync(0xffffffffu, acc, 2);
        acc += __shfl_xor_sync(0xffffffffu, acc, 4);
        acc += __shfl_xor_sync(0xffffffffu, acc, 8);
        float yv = fmaf(dv, zv, acc);
        if (ln == 0) yp[(size_t)l * HH] = yv;
    }

    // store chunk-final state (coalesced float4 per lane)
    float4 vr, vi;
    upk2(sr01, vr.x, vr.y); upk2(sr23, vr.z, vr.w);
    upk2(si01, vi.x, vi.y); upk2(si23, vi.z, vi.w);
    size_t so = (size_t)unit * NN + ln * 4;
    *reinterpret_cast<float4*>(&g_esr[so]) = vr;
    *reinterpret_cast<float4*>(&g_esi[so]) = vi;
}

// ------------------------------------------------------------------
// Combine: S_0 = 0; S_{c+1} = dA^CLEN * S_c + E_c.  Thread per (seq, n).
// ------------------------------------------------------------------
__global__ void combine_kernel() {
    int t = blockIdx.x * blockDim.x + threadIdx.x;   // 0 .. B*H*NN-1
    int seq = t >> 6;
    int n   = t & 63;
    int h   = seq & 255;
    float apr = g_apr[h * NN + n];
    float api = g_api[h * NN + n];
    float sr = 0.0f, si = 0.0f;
    #pragma unroll
    for (int c = 0; c < CH - 1; ++c) {
        size_t eo = (size_t)(seq * CH + c) * NN + n;
        float er = g_esr[eo], ei = g_esi[eo];
        float nsr = apr * sr - api * si + er;
        float nsi = apr * si + api * sr + ei;
        sr = nsr; si = nsi;
        size_t io = (size_t)(seq * CH + c + 1) * NN + n;
        g_isr[io] = sr;
        g_isi[io] = si;
    }
}

// ------------------------------------------------------------------
// Scan pass 2: correction for chunks 1..CH-1.
// y[t] += Re(sum_n u_t),  u_0 = w2 .* dA .* S_init,  u_{t+1} = dA .* u_t
// ------------------------------------------------------------------
__global__ void scan2_kernel() {
    int warp = (blockIdx.x * blockDim.x + threadIdx.x) >> 5;
    int lane = threadIdx.x & 31;
    int half = lane >> 4;
    int ln   = lane & 15;
    int unit = warp * 2 + half;          // 0 .. B*H*(CH-1)-1
    int seq  = unit / (CH - 1);
    int c    = unit - seq * (CH - 1) + 1;   // 1..CH-1
    int b = seq >> 8;
    int h = seq & 255;
    int base = h * NN + ln * 4;

    float a0r = g_ar[base+0], a1r = g_ar[base+1], a2r = g_ar[base+2], a3r = g_ar[base+3];
    float a0i = g_ai[base+0], a1i = g_ai[base+1], a2i = g_ai[base+2], a3i = g_ai[base+3];
    float w0r = g_wr[base+0], w1r = g_wr[base+1], w2r = g_wr[base+2], w3r = g_wr[base+3];
    float w0n = g_win[base+0], w1n = g_win[base+1], w2n = g_win[base+2], w3n = g_win[base+3];

    ull ar01 = pk2(a0r, a1r), ar23 = pk2(a2r, a3r);
    ull ai01 = pk2(a0i, a1i), ai23 = pk2(a2i, a3i);
    ull an01 = pk2(-a0i, -a1i), an23 = pk2(-a2i, -a3i);

    size_t io = (size_t)(seq * CH + c) * NN + ln * 4;
    float4 s_r = *reinterpret_cast<const float4*>(&g_isr[io]);
    float4 s_i = *reinterpret_cast<const float4*>(&g_isi[io]);
    ull sr01 = pk2(s_r.x, s_r.y), sr23 = pk2(s_r.z, s_r.w);
    ull si01 = pk2(s_i.x, s_i.y), si23 = pk2(s_i.z, s_i.w);

    // t = dA * S_init
    ull tr01 = fma2(ar01, sr01, mul2(an01, si01));
    ull ti01 = fma2(ai01, sr01, mul2(ar01, si01));
    ull tr23 = fma2(ar23, sr23, mul2(an23, si23));
    ull ti23 = fma2(ai23, sr23, mul2(ar23, si23));

    // u = w2 .* t   (Re(w2)=wr, Im(w2)=-wn)
    ull wr01 = pk2(w0r, w1r), wr23 = pk2(w2r, w3r);
    ull wn01 = pk2(w0n, w1n), wn23 = pk2(w2n, w3n);
    ull wm01 = pk2(-w0n, -w1n), wm23 = pk2(-w2n, -w3n);   // -wn = Im(w2)
    ull ur01 = fma2(wr01, tr01, mul2(wn01, ti01));        // Re = wr*tr + wn*ti
    ull ui01 = fma2(wr01, ti01, mul2(wm01, tr01));        // Im = wr*ti - wn*tr
    ull ur23 = fma2(wr23, tr23, mul2(wn23, ti23));
    ull ui23 = fma2(wr23, ti23, mul2(wm23, tr23));

    float* yp = g_y + ((size_t)b * LL + (size_t)c * CLEN) * HH + h;

    #pragma unroll 4
    for (int l = 0; l < CLEN; ++l) {
        // emit Re(sum u)
        ull sm = add2(ur01, ur23);
        float alo, ahi;
        upk2(sm, alo, ahi);
        float acc = alo + ahi;
        acc += __shfl_xor_sync(0xffffffffu, acc, 1);
        acc += __shfl_xor_sync(0xffffffffu, acc, 2);
        acc += __shfl_xor_sync(0xffffffffu, acc, 4);
        acc += __shfl_xor_sync(0xffffffffu, acc, 8);
        if (ln == 0) yp[(size_t)l * HH] += acc;
        // u = dA * u
        ull m0 = mul2(an01, ui01);
        ui01 = fma2(ai01, ur01, mul2(ar01, ui01));
        ur01 = fma2(ar01, ur01, m0);
        ull m1 = mul2(an23, ui23);
        ui23 = fma2(ai23, ur23, mul2(ar23, ui23));
        ur23 = fma2(ar23, ur23, m1);
    }
}

// ------------------------------------------------------------------
// gelu (tanh approx), in place
// ------------------------------------------------------------------
__global__ void gelu_kernel() {
    const float c0 = 0.7978845608028654f;
    const float c1 = 0.044715f;
    int n4 = (BB * LL * HH) / 4;
    for (int i = blockIdx.x * blockDim.x + threadIdx.x; i < n4;
         i += gridDim.x * blockDim.x) {
        float4 v = reinterpret_cast<float4*>(g_y)[i];
        float r[4] = {v.x, v.y, v.z, v.w};
        #pragma unroll
        for (int j = 0; j < 4; ++j) {
            float xv = r[j];
            float t = tanhf(c0 * (xv + c1 * xv * xv * xv));
            r[j] = 0.5f * xv * (1.0f + t);
        }
        reinterpret_cast<float4*>(g_y)[i] = make_float4(r[0], r[1], r[2], r[3]);
    }
}

// ------------------------------------------------------------------
// Fused GLU GEMM: h += (Y@W1^T + b1) * sigmoid(Y@W2^T + b2)
// ------------------------------------------------------------------
#define GBM 64
#define GBN 64
#define GBK 16
__global__ void glu_gemm_kernel(const float* __restrict__ W1,
                                const float* __restrict__ W2,
                                const float* __restrict__ b1,
                                const float* __restrict__ b2) {
    __shared__ float As [GBK][68];
    __shared__ float Bs1[GBK][68];
    __shared__ float Bs2[GBK][68];
    int tid = threadIdx.x;
    int m0 = blockIdx.x * GBM;
    int n0 = blockIdx.y * GBN;
    int ty = tid >> 4, tx = tid & 15;
    int lm = tid >> 2;
    int lk = (tid & 3) << 2;

    ull acc1[4][2], acc2[4][2];
    #pragma unroll
    for (int i = 0; i < 4; ++i)
        for (int p = 0; p < 2; ++p) { acc1[i][p] = 0ULL; acc2[i][p] = 0ULL; }

    for (int kt = 0; kt < HH / GBK; ++kt) {
        int k0 = kt * GBK;
        float4 av = *reinterpret_cast<const float4*>(
            &g_y[(size_t)(m0 + lm) * HH + k0 + lk]);
        float4 w1v = *reinterpret_cast<const float4*>(
            &W1[(size_t)(n0 + lm) * HH + k0 + lk]);
        float4 w2v = *reinterpret_cast<const float4*>(
            &W2[(size_t)(n0 + lm) * HH + k0 + lk]);
        __syncthreads();
        As [lk+0][lm] = av.x;  As [lk+1][lm] = av.y;
        As [lk+2][lm] = av.z;  As [lk+3][lm] = av.w;
        Bs1[lk+0][lm] = w1v.x; Bs1[lk+1][lm] = w1v.y;
        Bs1[lk+2][lm] = w1v.z; Bs1[lk+3][lm] = w1v.w;
        Bs2[lk+0][lm] = w2v.x; Bs2[lk+1][lm] = w2v.y;
        Bs2[lk+2][lm] = w2v.z; Bs2[lk+3][lm] = w2v.w;
        __syncthreads();
        #pragma unroll
        for (int k = 0; k < GBK; ++k) {
            float4 a   = *reinterpret_cast<const float4*>(&As [k][ty * 4]);
            float4 bv1 = *reinterpret_cast<const float4*>(&Bs1[k][tx * 4]);
            float4 bv2 = *reinterpret_cast<const float4*>(&Bs2[k][tx * 4]);
            ull b1p0 = pk2(bv1.x, bv1.y), b1p1 = pk2(bv1.z, bv1.w);
            ull b2p0 = pk2(bv2.x, bv2.y), b2p1 = pk2(bv2.z, bv2.w);
            float avr[4] = {a.x, a.y, a.z, a.w};
            #pragma unroll
            for (int i = 0; i < 4; ++i) {
                ull aa = pk2(avr[i], avr[i]);
                acc1[i][0] = fma2(aa, b1p0, acc1[i][0]);
                acc1[i][1] = fma2(aa, b1p1, acc1[i][1]);
                acc2[i][0] = fma2(aa, b2p0, acc2[i][0]);
                acc2[i][1] = fma2(aa, b2p1, acc2[i][1]);
            }
        }
    }

    float bb1[4], bb2[4];
    #pragma unroll
    for (int j = 0; j < 4; ++j) {
        bb1[j] = b1[n0 + tx * 4 + j];
        bb2[j] = b2[n0 + tx * 4 + j];
    }
    #pragma unroll
    for (int i = 0; i < 4; ++i) {
        int row = m0 + ty * 4 + i;
        float* hp = &g_h[(size_t)row * HH + n0 + tx * 4];
        float4 hv = *reinterpret_cast<float4*>(hp);
        float g1v[4], g2v[4];
        upk2(acc1[i][0], g1v[0], g1v[1]); upk2(acc1[i][1], g1v[2], g1v[3]);
        upk2(acc2[i][0], g2v[0], g2v[1]); upk2(acc2[i][1], g2v[2], g2v[3]);
        float hvv[4] = {hv.x, hv.y, hv.z, hv.w};
        float o[4];
        #pragma unroll
        for (int j = 0; j < 4; ++j) {
            float gate = g2v[j] + bb2[j];
            float sig  = 1.0f / (1.0f + expf(-gate));
            o[j] = hvv[j] + (g1v[j] + bb1[j]) * sig;
        }
        *reinterpret_cast<float4*>(hp) = make_float4(o[0], o[1], o[2], o[3]);
    }
}

// ------------------------------------------------------------------
// Decoder: out[m, o] = sum_h h[m,h]*dec_w[o,h] + dec_b[o]
// ------------------------------------------------------------------
__global__ void dec_kernel(const float* __restrict__ dw,
                           const float* __restrict__ db,
                           float* __restrict__ out) {
    int warp = (blockIdx.x * blockDim.x + threadIdx.x) >> 5;
    int lane = threadIdx.x & 31;
    const float* row = g_h + (size_t)warp * HH;
    float hr[8];
    #pragma unroll
    for (int k = 0; k < 8; ++k) hr[k] = row[lane + 32 * k];
    for (int o = 0; o < OUTD; ++o) {
        const float* wrow = dw + o * HH + lane;
        float acc = 0.0f;
        #pragma unroll
        for (int k = 0; k < 8; ++k) acc = fmaf(hr[k], wrow[32 * k], acc);
        #pragma unroll
        for (int m = 16; m; m >>= 1) acc += __shfl_xor_sync(0xffffffffu, acc, m);
        if (lane == 0) out[(size_t)warp * OUTD + o] = acc + db[o];
    }
}

// ------------------------------------------------------------------
extern "C" void kernel_launch(void* const* d_in, const int* in_sizes, int n_in,
                              void* d_out, int out_size) {
    const float* x     = (const float*)d_in[0];
    const float* enc_w = (const float*)d_in[1];
    const float* enc_b = (const float*)d_in[2];
    const float* lre   = (const float*)d_in[3];
    const float* lim   = (const float*)d_in[4];
    const float* cre   = (const float*)d_in[5];
    const float* cim   = (const float*)d_in[6];
    const float* dd    = (const float*)d_in[7];
    const float* lstep = (const float*)d_in[8];
    const float* lns   = (const float*)d_in[9];
    const float* lnb   = (const float*)d_in[10];
    const float* ow    = (const float*)d_in[11];
    const float* ob    = (const float*)d_in[12];
    const float* o2w   = (const float*)d_in[13];
    const float* o2b   = (const float*)d_in[14];
    const float* dw    = (const float*)d_in[15];
    const float* db    = (const float*)d_in[16];
    float* out = (float*)d_out;

    enc_kernel<<<(BB * LL) / 16, 256>>>(x, enc_w, enc_b);

    for (int li = 0; li < NLAY; ++li) {
        ln_kernel<<<(BB * LL) / 8, 256>>>(lns + li * HH, lnb + li * HH);
        ssm_params_kernel<<<(HH * NN) / 256, 256>>>(
            lre + li * HH * NN, lim + li * HH * NN,
            cre + li * HH * NN, cim + li * HH * NN, lstep + li * HH);
        // pass 1: B*H*CH units, 2 per warp, 8 warps/block
        scan1_kernel<<<(BB * HH * CH) / 16, 256>>>(dd + li * HH);
        combine_kernel<<<(BB * HH * NN) / 256, 256>>>();
        // pass 2: B*H*(CH-1) units
        scan2_kernel<<<(BB * HH * (CH - 1)) / 16, 256>>>();
        gelu_kernel<<<1024, 256>>>();
        glu_gemm_kernel<<<dim3((BB * LL) / GBM, HH / GBN), 256>>>(
            ow + li * HH * HH, o2w + li * HH * HH,
            ob + li * HH, o2b + li * HH);
    }

    dec_kernel<<<(BB * LL) / 8, 256>>>(dw, db, out);
}

// round 3
// speedup vs baseline: 1.7363x; 1.3329x over previous
#include <cuda_runtime.h>
#include <math.h>

// Problem dims (fixed)
#define BB   16
#define LL   2048
#define HH   256
#define NN   64
#define NLAY 4
#define IND  40
#define OUTD 33

// Chunked-scan config
#define CH    4
#define CLEN  512   // LL / CH

typedef unsigned long long ull;

// ------------------------------------------------------------------
// Scratch (device globals)
// ------------------------------------------------------------------
__device__ float g_h[BB * LL * HH];   // residual stream, [m][h]
__device__ float g_zt[BB * HH * LL];  // layernorm output, TRANSPOSED [seq][l]
__device__ float g_yt[BB * HH * LL];  // SSM/gelu output, TRANSPOSED [seq][l]
__device__ float g_ar[HH * NN];
__device__ float g_ai[HH * NN];
__device__ float g_wr[HH * NN];
__device__ float g_win[HH * NN];
__device__ float g_apr[HH * NN];      // Re(dA^CLEN)
__device__ float g_api[HH * NN];      // Im(dA^CLEN)
__device__ float g_esr[BB * HH * CH * NN];
__device__ float g_esi[BB * HH * CH * NN];
__device__ float g_isr[BB * HH * CH * NN];
__device__ float g_isi[BB * HH * CH * NN];

// ------------------------------------------------------------------
// f32x2 packed math (Blackwell)
// ------------------------------------------------------------------
__device__ __forceinline__ ull pk2(float lo, float hi) {
    ull r;
    asm("mov.b64 %0, {%1, %2};" : "=l"(r) : "f"(lo), "f"(hi));
    return r;
}
__device__ __forceinline__ void upk2(ull v, float& lo, float& hi) {
    asm("mov.b64 {%0, %1}, %2;" : "=f"(lo), "=f"(hi) : "l"(v));
}
__device__ __forceinline__ ull fma2(ull a, ull b, ull c) {
    ull d;
    asm("fma.rn.f32x2 %0, %1, %2, %3;" : "=l"(d) : "l"(a), "l"(b), "l"(c));
    return d;
}
__device__ __forceinline__ ull mul2(ull a, ull b) {
    ull d;
    asm("mul.rn.f32x2 %0, %1, %2;" : "=l"(d) : "l"(a), "l"(b));
    return d;
}
__device__ __forceinline__ ull add2(ull a, ull b) {
    ull d;
    asm("add.rn.f32x2 %0, %1, %2;" : "=l"(d) : "l"(a), "l"(b));
    return d;
}

// ------------------------------------------------------------------
// Encoder: h[m, :] = enc_w @ x[m, :] + enc_b
// ------------------------------------------------------------------
__global__ void enc_kernel(const float* __restrict__ x,
                           const float* __restrict__ ew,
                           const float* __restrict__ eb) {
    __shared__ float sw[IND * HH];
    __shared__ float sx[16 * IND];
    int tid = threadIdx.x;
    for (int idx = tid; idx < HH * IND; idx += 256) {
        int h = idx / IND, i = idx % IND;
        sw[i * HH + h] = ew[idx];
    }
    int m0 = blockIdx.x * 16;
    for (int idx = tid; idx < 16 * IND; idx += 256)
        sx[idx] = x[(size_t)m0 * IND + idx];
    __syncthreads();
    float bias = eb[tid];
    for (int r = 0; r < 16; ++r) {
        float acc = bias;
        #pragma unroll
        for (int i = 0; i < IND; ++i)
            acc = fmaf(sx[r * IND + i], sw[i * HH + tid], acc);
        g_h[(size_t)(m0 + r) * HH + tid] = acc;
    }
}

// ------------------------------------------------------------------
// LayerNorm + transpose: reads g_h [m][h], writes g_zt [b*H+h][l].
// Block handles 32 rows; smem-tiled transposed write (coalesced).
// ------------------------------------------------------------------
__global__ void ln_kernel(const float* __restrict__ sc,
                          const float* __restrict__ bi) {
    __shared__ float sm[32][257];
    int tid  = threadIdx.x;
    int warp = tid >> 5;
    int lane = tid & 31;
    int m0 = blockIdx.x * 32;

    for (int r = warp; r < 32; r += 8) {
        const float* row = g_h + (size_t)(m0 + r) * HH;
        float4 v0 = *reinterpret_cast<const float4*>(row + lane * 4);
        float4 v1 = *reinterpret_cast<const float4*>(row + 128 + lane * 4);
        float s = v0.x + v0.y + v0.z + v0.w + v1.x + v1.y + v1.z + v1.w;
        float q = v0.x*v0.x + v0.y*v0.y + v0.z*v0.z + v0.w*v0.w
                + v1.x*v1.x + v1.y*v1.y + v1.z*v1.z + v1.w*v1.w;
        #pragma unroll
        for (int m = 16; m; m >>= 1) {
            s += __shfl_xor_sync(0xffffffffu, s, m);
            q += __shfl_xor_sync(0xffffffffu, q, m);
        }
        float mu  = s * (1.0f / 256.0f);
        float var = q * (1.0f / 256.0f) - mu * mu;
        float inv = rsqrtf(var + 1e-5f);
        int h0 = lane * 4, h1 = 128 + lane * 4;
        sm[r][h0+0] = (v0.x - mu) * inv * sc[h0+0] + bi[h0+0];
        sm[r][h0+1] = (v0.y - mu) * inv * sc[h0+1] + bi[h0+1];
        sm[r][h0+2] = (v0.z - mu) * inv * sc[h0+2] + bi[h0+2];
        sm[r][h0+3] = (v0.w - mu) * inv * sc[h0+3] + bi[h0+3];
        sm[r][h1+0] = (v1.x - mu) * inv * sc[h1+0] + bi[h1+0];
        sm[r][h1+1] = (v1.y - mu) * inv * sc[h1+1] + bi[h1+1];
        sm[r][h1+2] = (v1.z - mu) * inv * sc[h1+2] + bi[h1+2];
        sm[r][h1+3] = (v1.w - mu) * inv * sc[h1+3] + bi[h1+3];
    }
    __syncthreads();

    int b  = m0 >> 11;        // m0 / LL
    int l0 = m0 & 2047;       // m0 % LL
    for (int h = warp; h < HH; h += 8) {
        g_zt[((size_t)(b * HH + h)) * LL + l0 + lane] = sm[lane][h];
    }
}

// ------------------------------------------------------------------
// S4D discretization + dA^CLEN (double) for chunk combine.
// ------------------------------------------------------------------
__global__ void ssm_params_kernel(const float* __restrict__ lre,
                                  const float* __restrict__ lim,
                                  const float* __restrict__ cre,
                                  const float* __restrict__ cim,
                                  const float* __restrict__ lstep) {
    int idx = blockIdx.x * blockDim.x + threadIdx.x;
    if (idx >= HH * NN) return;
    int h = idx >> 6;
    float Lre = lre[idx], Lim = lim[idx];
    float Cre = cre[idx], Cim = cim[idx];
    float dt  = expf(lstep[h]);
    float mag = expf(Lre * dt);
    float th  = Lim * dt;
    float dar = mag * cosf(th);
    float dai = mag * sinf(th);
    float den = Lre * Lre + Lim * Lim;
    float nr = dar - 1.0f, ni = dai;
    float dbr = (nr * Lre + ni * Lim) / den;
    float dbi = (ni * Lre - nr * Lim) / den;
    float wr = Cre * dbr - Cim * dbi;
    float wi = Cre * dbi + Cim * dbr;
    g_ar[idx]  = dar;
    g_ai[idx]  = dai;
    g_wr[idx]  = 2.0f * wr;
    g_win[idx] = -2.0f * wi;
    double dtd = exp((double)lstep[h]);
    double mr  = exp((double)Lre * dtd * (double)CLEN);
    double thd = (double)Lim * dtd * (double)CLEN;
    g_apr[idx] = (float)(mr * cos(thd));
    g_api[idx] = (float)(mr * sin(thd));
}

// ------------------------------------------------------------------
// Scan pass 1 (transposed I/O, 16-step tiles, reduce-scatter).
// 2 units/warp; 16 lanes/unit; 4 complex states/lane.
// ------------------------------------------------------------------
__global__ void __launch_bounds__(256, 4) scan1_kernel(const float* __restrict__ dcoef) {
    int warp = (blockIdx.x * blockDim.x + threadIdx.x) >> 5;
    int lane = threadIdx.x & 31;
    int half = lane >> 4;
    int ln   = lane & 15;
    int unit = warp * 2 + half;        // 0..B*H*CH-1
    int seq  = unit >> 2;              // unit / CH
    int c    = unit & (CH - 1);
    int h = seq & 255;
    int base = h * NN + ln * 4;

    float a0r = g_ar[base+0], a1r = g_ar[base+1], a2r = g_ar[base+2], a3r = g_ar[base+3];
    float a0i = g_ai[base+0], a1i = g_ai[base+1], a2i = g_ai[base+2], a3i = g_ai[base+3];
    float w0r = g_wr[base+0], w1r = g_wr[base+1], w2r = g_wr[base+2], w3r = g_wr[base+3];
    float w0n = g_win[base+0], w1n = g_win[base+1], w2n = g_win[base+2], w3n = g_win[base+3];

    ull ar01 = pk2(a0r, a1r), ar23 = pk2(a2r, a3r);
    ull ai01 = pk2(a0i, a1i), ai23 = pk2(a2i, a3i);
    ull an01 = pk2(-a0i, -a1i), an23 = pk2(-a2i, -a3i);
    ull wr01 = pk2(w0r, w1r), wr23 = pk2(w2r, w3r);
    ull wn01 = pk2(w0n, w1n), wn23 = pk2(w2n, w3n);

    ull sr01 = 0ULL, si01 = 0ULL, sr23 = 0ULL, si23 = 0ULL;

    const float* zp = g_zt + (size_t)seq * LL + (size_t)c * CLEN;
    float*       yp = g_yt + (size_t)seq * LL + (size_t)c * CLEN;
    float dv = dcoef[h];

    for (int l0 = 0; l0 < CLEN; l0 += 16) {
        float zv = zp[l0 + ln];
        float c16[16];
        #pragma unroll
        for (int t = 0; t < 16; ++t) {
            float zb = __shfl_sync(0xffffffffu, zv, t, 16);
            ull z2 = pk2(zb, zb);
            ull t0 = fma2(an01, si01, z2);
            si01   = fma2(ai01, sr01, mul2(ar01, si01));
            sr01   = fma2(ar01, sr01, t0);
            ull t1 = fma2(an23, si23, z2);
            si23   = fma2(ai23, sr23, mul2(ar23, si23));
            sr23   = fma2(ar23, sr23, t1);
            ull av = fma2(wr01, sr01, mul2(wn01, si01));
            av = fma2(wr23, sr23, av);
            av = fma2(wn23, si23, av);
            float alo, ahi;
            upk2(av, alo, ahi);
            c16[t] = alo + ahi;
        }
        // reduce-scatter across 16 lanes: lane ln ends with sum for t=ln
        #pragma unroll
        for (int off = 8; off >= 1; off >>= 1) {
            bool up = (ln & off) != 0;
            #pragma unroll
            for (int j = 0; j < off; ++j) {
                float send = up ? c16[j] : c16[j + off];
                float keep = up ? c16[j + off] : c16[j];
                c16[j] = keep + __shfl_xor_sync(0xffffffffu, send, off, 16);
            }
        }
        yp[l0 + ln] = fmaf(dv, zv, c16[0]);
    }

    float4 vr, vi;
    upk2(sr01, vr.x, vr.y); upk2(sr23, vr.z, vr.w);
    upk2(si01, vi.x, vi.y); upk2(si23, vi.z, vi.w);
    size_t so = (size_t)unit * NN + ln * 4;
    *reinterpret_cast<float4*>(&g_esr[so]) = vr;
    *reinterpret_cast<float4*>(&g_esi[so]) = vi;
}

// ------------------------------------------------------------------
// Combine: S_0 = 0; S_{c+1} = dA^CLEN * S_c + E_c.
// ------------------------------------------------------------------
__global__ void combine_kernel() {
    int t = blockIdx.x * blockDim.x + threadIdx.x;
    int seq = t >> 6;
    int n   = t & 63;
    int h   = seq & 255;
    float apr = g_apr[h * NN + n];
    float api = g_api[h * NN + n];
    float sr = 0.0f, si = 0.0f;
    #pragma unroll
    for (int c = 0; c < CH - 1; ++c) {
        size_t eo = (size_t)(seq * CH + c) * NN + n;
        float er = g_esr[eo], ei = g_esi[eo];
        float nsr = apr * sr - api * si + er;
        float nsi = apr * si + api * sr + ei;
        sr = nsr; si = nsi;
        size_t io = (size_t)(seq * CH + c + 1) * NN + n;
        g_isr[io] = sr;
        g_isi[io] = si;
    }
}

// ------------------------------------------------------------------
// Scan pass 2: y[t] += Re(sum_n u_t); u_0 = w2.*dA.*S_init; u *= dA.
// ------------------------------------------------------------------
__global__ void __launch_bounds__(256, 4) scan2_kernel() {
    int warp = (blockIdx.x * blockDim.x + threadIdx.x) >> 5;
    int lane = threadIdx.x & 31;
    int half = lane >> 4;
    int ln   = lane & 15;
    int unit = warp * 2 + half;
    int seq  = unit / (CH - 1);
    int c    = unit - seq * (CH - 1) + 1;
    int h = seq & 255;
    int base = h * NN + ln * 4;

    float a0r = g_ar[base+0], a1r = g_ar[base+1], a2r = g_ar[base+2], a3r = g_ar[base+3];
    float a0i = g_ai[base+0], a1i = g_ai[base+1], a2i = g_ai[base+2], a3i = g_ai[base+3];
    float w0r = g_wr[base+0], w1r = g_wr[base+1], w2r = g_wr[base+2], w3r = g_wr[base+3];
    float w0n = g_win[base+0], w1n = g_win[base+1], w2n = g_win[base+2], w3n = g_win[base+3];

    ull ar01 = pk2(a0r, a1r), ar23 = pk2(a2r, a3r);
    ull ai01 = pk2(a0i, a1i), ai23 = pk2(a2i, a3i);
    ull an01 = pk2(-a0i, -a1i), an23 = pk2(-a2i, -a3i);

    size_t io = (size_t)(seq * CH + c) * NN + ln * 4;
    float4 s_r = *reinterpret_cast<const float4*>(&g_isr[io]);
    float4 s_i = *reinterpret_cast<const float4*>(&g_isi[io]);
    ull sr01 = pk2(s_r.x, s_r.y), sr23 = pk2(s_r.z, s_r.w);
    ull si01 = pk2(s_i.x, s_i.y), si23 = pk2(s_i.z, s_i.w);

    ull tr01 = fma2(ar01, sr01, mul2(an01, si01));
    ull ti01 = fma2(ai01, sr01, mul2(ar01, si01));
    ull tr23 = fma2(ar23, sr23, mul2(an23, si23));
    ull ti23 = fma2(ai23, sr23, mul2(ar23, si23));

    ull wr01 = pk2(w0r, w1r), wr23 = pk2(w2r, w3r);
    ull wn01 = pk2(w0n, w1n), wn23 = pk2(w2n, w3n);
    ull wm01 = pk2(-w0n, -w1n), wm23 = pk2(-w2n, -w3n);
    ull ur01 = fma2(wr01, tr01, mul2(wn01, ti01));
    ull ui01 = fma2(wr01, ti01, mul2(wm01, tr01));
    ull ur23 = fma2(wr23, tr23, mul2(wn23, ti23));
    ull ui23 = fma2(wr23, ti23, mul2(wm23, tr23));

    float* yp = g_yt + (size_t)seq * LL + (size_t)c * CLEN;

    for (int l0 = 0; l0 < CLEN; l0 += 16) {
        float c16[16];
        #pragma unroll
        for (int t = 0; t < 16; ++t) {
            ull sm = add2(ur01, ur23);
            float alo, ahi;
            upk2(sm, alo, ahi);
            c16[t] = alo + ahi;
            ull m0 = mul2(an01, ui01);
            ui01 = fma2(ai01, ur01, mul2(ar01, ui01));
            ur01 = fma2(ar01, ur01, m0);
            ull m1 = mul2(an23, ui23);
            ui23 = fma2(ai23, ur23, mul2(ar23, ui23));
            ur23 = fma2(ar23, ur23, m1);
        }
        #pragma unroll
        for (int off = 8; off >= 1; off >>= 1) {
            bool up = (ln & off) != 0;
            #pragma unroll
            for (int j = 0; j < off; ++j) {
                float send = up ? c16[j] : c16[j + off];
                float keep = up ? c16[j + off] : c16[j];
                c16[j] = keep + __shfl_xor_sync(0xffffffffu, send, off, 16);
            }
        }
        yp[l0 + ln] += c16[0];
    }
}

// ------------------------------------------------------------------
// gelu (tanh approx), in place on g_yt
// ------------------------------------------------------------------
__global__ void gelu_kernel() {
    const float c0 = 0.7978845608028654f;
    const float c1 = 0.044715f;
    int n4 = (BB * LL * HH) / 4;
    for (int i = blockIdx.x * blockDim.x + threadIdx.x; i < n4;
         i += gridDim.x * blockDim.x) {
        float4 v = reinterpret_cast<float4*>(g_yt)[i];
        float r[4] = {v.x, v.y, v.z, v.w};
        #pragma unroll
        for (int j = 0; j < 4; ++j) {
            float xv = r[j];
            float t = tanhf(c0 * (xv + c1 * xv * xv * xv));
            r[j] = 0.5f * xv * (1.0f + t);
        }
        reinterpret_cast<float4*>(g_yt)[i] = make_float4(r[0], r[1], r[2], r[3]);
    }
}

// ------------------------------------------------------------------
// Fused GLU GEMM: h += (Y@W1^T + b1) * sigmoid(Y@W2^T + b2)
// Y read from TRANSPOSED g_yt ([h][b*L]-style), natively [k][m].
// ------------------------------------------------------------------
#define GBM 64
#define GBN 64
#define GBK 16
__global__ void glu_gemm_kernel(const float* __restrict__ W1,
                                const float* __restrict__ W2,
                                const float* __restrict__ b1,
                                const float* __restrict__ b2) {
    __shared__ float As [GBK][68];
    __shared__ float Bs1[GBK][68];
    __shared__ float Bs2[GBK][68];
    int tid = threadIdx.x;
    int m0 = blockIdx.x * GBM;
    int n0 = blockIdx.y * GBN;
    int b  = m0 >> 11;           // m0 / LL
    int l0 = m0 & 2047;          // m0 % LL
    int ty = tid >> 4, tx = tid & 15;
    int lm = tid >> 2;
    int lk = (tid & 3) << 2;
    int ak = tid >> 4;           // 0..15 (k for A load)
    int am = (tid & 15) << 2;    // 0..60 (m quad for A load)

    ull acc1[4][2], acc2[4][2];
    #pragma unroll
    for (int i = 0; i < 4; ++i)
        for (int p = 0; p < 2; ++p) { acc1[i][p] = 0ULL; acc2[i][p] = 0ULL; }

    for (int kt = 0; kt < HH / GBK; ++kt) {
        int k0 = kt * GBK;
        float4 av = *reinterpret_cast<const float4*>(
            &g_yt[((size_t)(b * HH + k0 + ak)) * LL + l0 + am]);
        float4 w1v = *reinterpret_cast<const float4*>(
            &W1[(size_t)(n0 + lm) * HH + k0 + lk]);
        float4 w2v = *reinterpret_cast<const float4*>(
            &W2[(size_t)(n0 + lm) * HH + k0 + lk]);
        __syncthreads();
        *reinterpret_cast<float4*>(&As[ak][am]) = av;
        Bs1[lk+0][lm] = w1v.x; Bs1[lk+1][lm] = w1v.y;
        Bs1[lk+2][lm] = w1v.z; Bs1[lk+3][lm] = w1v.w;
        Bs2[lk+0][lm] = w2v.x; Bs2[lk+1][lm] = w2v.y;
        Bs2[lk+2][lm] = w2v.z; Bs2[lk+3][lm] = w2v.w;
        __syncthreads();
        #pragma unroll
        for (int k = 0; k < GBK; ++k) {
            float4 a   = *reinterpret_cast<const float4*>(&As [k][ty * 4]);
            float4 bv1 = *reinterpret_cast<const float4*>(&Bs1[k][tx * 4]);
            float4 bv2 = *reinterpret_cast<const float4*>(&Bs2[k][tx * 4]);
            ull b1p0 = pk2(bv1.x, bv1.y), b1p1 = pk2(bv1.z, bv1.w);
            ull b2p0 = pk2(bv2.x, bv2.y), b2p1 = pk2(bv2.z, bv2.w);
            float avr[4] = {a.x, a.y, a.z, a.w};
            #pragma unroll
            for (int i = 0; i < 4; ++i) {
                ull aa = pk2(avr[i], avr[i]);
                acc1[i][0] = fma2(aa, b1p0, acc1[i][0]);
                acc1[i][1] = fma2(aa, b1p1, acc1[i][1]);
                acc2[i][0] = fma2(aa, b2p0, acc2[i][0]);
                acc2[i][1] = fma2(aa, b2p1, acc2[i][1]);
            }
        }
    }

    float bb1[4], bb2[4];
    #pragma unroll
    for (int j = 0; j < 4; ++j) {
        bb1[j] = b1[n0 + tx * 4 + j];
        bb2[j] = b2[n0 + tx * 4 + j];
    }
    #pragma unroll
    for (int i = 0; i < 4; ++i) {
        int row = m0 + ty * 4 + i;
        float* hp = &g_h[(size_t)row * HH + n0 + tx * 4];
        float4 hv = *reinterpret_cast<float4*>(hp);
        float g1v[4], g2v[4];
        upk2(acc1[i][0], g1v[0], g1v[1]); upk2(acc1[i][1], g1v[2], g1v[3]);
        upk2(acc2[i][0], g2v[0], g2v[1]); upk2(acc2[i][1], g2v[2], g2v[3]);
        float hvv[4] = {hv.x, hv.y, hv.z, hv.w};
        float o[4];
        #pragma unroll
        for (int j = 0; j < 4; ++j) {
            float gate = g2v[j] + bb2[j];
            float sig  = 1.0f / (1.0f + expf(-gate));
            o[j] = hvv[j] + (g1v[j] + bb1[j]) * sig;
        }
        *reinterpret_cast<float4*>(hp) = make_float4(o[0], o[1], o[2], o[3]);
    }
}

// ------------------------------------------------------------------
// Decoder: out[m, o] = sum_h h[m,h]*dec_w[o,h] + dec_b[o]
// ------------------------------------------------------------------
__global__ void dec_kernel(const float* __restrict__ dw,
                           const float* __restrict__ db,
                           float* __restrict__ out) {
    int warp = (blockIdx.x * blockDim.x + threadIdx.x) >> 5;
    int lane = threadIdx.x & 31;
    const float* row = g_h + (size_t)warp * HH;
    float hr[8];
    #pragma unroll
    for (int k = 0; k < 8; ++k) hr[k] = row[lane + 32 * k];
    for (int o = 0; o < OUTD; ++o) {
        const float* wrow = dw + o * HH + lane;
        float acc = 0.0f;
        #pragma unroll
        for (int k = 0; k < 8; ++k) acc = fmaf(hr[k], wrow[32 * k], acc);
        #pragma unroll
        for (int m = 16; m; m >>= 1) acc += __shfl_xor_sync(0xffffffffu, acc, m);
        if (lane == 0) out[(size_t)warp * OUTD + o] = acc + db[o];
    }
}

// ------------------------------------------------------------------
extern "C" void kernel_launch(void* const* d_in, const int* in_sizes, int n_in,
                              void* d_out, int out_size) {
    const float* x     = (const float*)d_in[0];
    const float* enc_w = (const float*)d_in[1];
    const float* enc_b = (const float*)d_in[2];
    const float* lre   = (const float*)d_in[3];
    const float* lim   = (const float*)d_in[4];
    const float* cre   = (const float*)d_in[5];
    const float* cim   = (const float*)d_in[6];
    const float* dd    = (const float*)d_in[7];
    const float* lstep = (const float*)d_in[8];
    const float* lns   = (const float*)d_in[9];
    const float* lnb   = (const float*)d_in[10];
    const float* ow    = (const float*)d_in[11];
    const float* ob    = (const float*)d_in[12];
    const float* o2w   = (const float*)d_in[13];
    const float* o2b   = (const float*)d_in[14];
    const float* dw    = (const float*)d_in[15];
    const float* db    = (const float*)d_in[16];
    float* out = (float*)d_out;

    enc_kernel<<<(BB * LL) / 16, 256>>>(x, enc_w, enc_b);

    for (int li = 0; li < NLAY; ++li) {
        ln_kernel<<<(BB * LL) / 32, 256>>>(lns + li * HH, lnb + li * HH);
        ssm_params_kernel<<<(HH * NN) / 256, 256>>>(
            lre + li * HH * NN, lim + li * HH * NN,
            cre + li * HH * NN, cim + li * HH * NN, lstep + li * HH);
        scan1_kernel<<<(BB * HH * CH) / 16, 256>>>(dd + li * HH);
        combine_kernel<<<(BB * HH * NN) / 256, 256>>>();
        scan2_kernel<<<(BB * HH * (CH - 1)) / 16, 256>>>();
        gelu_kernel<<<1024, 256>>>();
        glu_gemm_kernel<<<dim3((BB * LL) / GBM, HH / GBN), 256>>>(
            ow + li * HH * HH, o2w + li * HH * HH,
            ob + li * HH, o2b + li * HH);
    }

    dec_kernel<<<(BB * LL) / 8, 256>>>(dw, db, out);
}

// round 5
// speedup vs baseline: 2.1294x; 1.2264x over previous
#include <cuda_runtime.h>
#include <math.h>
#include <stdint.h>

// Problem dims (fixed)
#define BB   16
#define LL   2048
#define HH   256
#define NN   64
#define NLAY 4
#define IND  40
#define OUTD 33

// Chunked-scan config
#define CH    4
#define CLEN  512   // LL / CH

typedef unsigned long long ull;

// ------------------------------------------------------------------
// Scratch (device globals)
// ------------------------------------------------------------------
__device__ float g_h[BB * LL * HH];   // residual stream, [m][h]
__device__ float g_zt[BB * HH * LL];  // layernorm output, TRANSPOSED [seq][l]
__device__ float g_yt[BB * HH * LL];  // SSM/gelu output, TRANSPOSED [seq][l]
__device__ float g_ar[HH * NN];
__device__ float g_ai[HH * NN];
__device__ float g_wr[HH * NN];
__device__ float g_win[HH * NN];
__device__ float g_apr[HH * NN];      // Re(dA^CLEN)
__device__ float g_api[HH * NN];      // Im(dA^CLEN)
__device__ float g_esr[BB * HH * CH * NN];
__device__ float g_esi[BB * HH * CH * NN];
__device__ float g_isr[BB * HH * CH * NN];
__device__ float g_isi[BB * HH * CH * NN];

// ------------------------------------------------------------------
// f32x2 packed math (Blackwell)
// ------------------------------------------------------------------
__device__ __forceinline__ ull pk2(float lo, float hi) {
    ull r;
    asm("mov.b64 %0, {%1, %2};" : "=l"(r) : "f"(lo), "f"(hi));
    return r;
}
__device__ __forceinline__ void upk2(ull v, float& lo, float& hi) {
    asm("mov.b64 {%0, %1}, %2;" : "=f"(lo), "=f"(hi) : "l"(v));
}
__device__ __forceinline__ ull fma2(ull a, ull b, ull c) {
    ull d;
    asm("fma.rn.f32x2 %0, %1, %2, %3;" : "=l"(d) : "l"(a), "l"(b), "l"(c));
    return d;
}
__device__ __forceinline__ ull mul2(ull a, ull b) {
    ull d;
    asm("mul.rn.f32x2 %0, %1, %2;" : "=l"(d) : "l"(a), "l"(b));
    return d;
}
__device__ __forceinline__ ull add2(ull a, ull b) {
    ull d;
    asm("add.rn.f32x2 %0, %1, %2;" : "=l"(d) : "l"(a), "l"(b));
    return d;
}

__device__ __forceinline__ float gelu1(float x) {
    const float c0 = 0.7978845608028654f;
    const float c1 = 0.044715f;
    float t = tanhf(c0 * (x + c1 * x * x * x));
    return 0.5f * x * (1.0f + t);
}

__device__ __forceinline__ uint32_t f2tf32(float x) {
    uint32_t r;
    asm("cvt.rna.tf32.f32 %0, %1;" : "=r"(r) : "f"(x));
    return r;
}

// mma.sync tf32 m16n8k8 (sm_80+, valid on target sm_103)
__device__ __forceinline__ void mma_tf32(float c[4],
                                         uint32_t a0, uint32_t a1,
                                         uint32_t a2, uint32_t a3,
                                         uint32_t b0, uint32_t b1) {
    asm volatile(
        "mma.sync.aligned.m16n8k8.row.col.f32.tf32.tf32.f32 "
        "{%0,%1,%2,%3}, {%4,%5,%6,%7}, {%8,%9}, {%0,%1,%2,%3};"
        : "+f"(c[0]), "+f"(c[1]), "+f"(c[2]), "+f"(c[3])
        : "r"(a0), "r"(a1), "r"(a2), "r"(a3), "r"(b0), "r"(b1));
}

// ------------------------------------------------------------------
// Encoder
// ------------------------------------------------------------------
__global__ void enc_kernel(const float* __restrict__ x,
                           const float* __restrict__ ew,
                           const float* __restrict__ eb) {
    __shared__ float sw[IND * HH];
    __shared__ float sx[16 * IND];
    int tid = threadIdx.x;
    for (int idx = tid; idx < HH * IND; idx += 256) {
        int h = idx / IND, i = idx % IND;
        sw[i * HH + h] = ew[idx];
    }
    int m0 = blockIdx.x * 16;
    for (int idx = tid; idx < 16 * IND; idx += 256)
        sx[idx] = x[(size_t)m0 * IND + idx];
    __syncthreads();
    float bias = eb[tid];
    for (int r = 0; r < 16; ++r) {
        float acc = bias;
        #pragma unroll
        for (int i = 0; i < IND; ++i)
            acc = fmaf(sx[r * IND + i], sw[i * HH + tid], acc);
        g_h[(size_t)(m0 + r) * HH + tid] = acc;
    }
}

// ------------------------------------------------------------------
// LayerNorm + transpose
// ------------------------------------------------------------------
__global__ void ln_kernel(const float* __restrict__ sc,
                          const float* __restrict__ bi) {
    __shared__ float sm[32][257];
    int tid  = threadIdx.x;
    int warp = tid >> 5;
    int lane = tid & 31;
    int m0 = blockIdx.x * 32;

    for (int r = warp; r < 32; r += 8) {
        const float* row = g_h + (size_t)(m0 + r) * HH;
        float4 v0 = *reinterpret_cast<const float4*>(row + lane * 4);
        float4 v1 = *reinterpret_cast<const float4*>(row + 128 + lane * 4);
        float s = v0.x + v0.y + v0.z + v0.w + v1.x + v1.y + v1.z + v1.w;
        float q = v0.x*v0.x + v0.y*v0.y + v0.z*v0.z + v0.w*v0.w
                + v1.x*v1.x + v1.y*v1.y + v1.z*v1.z + v1.w*v1.w;
        #pragma unroll
        for (int m = 16; m; m >>= 1) {
            s += __shfl_xor_sync(0xffffffffu, s, m);
            q += __shfl_xor_sync(0xffffffffu, q, m);
        }
        float mu  = s * (1.0f / 256.0f);
        float var = q * (1.0f / 256.0f) - mu * mu;
        float inv = rsqrtf(var + 1e-5f);
        int h0 = lane * 4, h1 = 128 + lane * 4;
        sm[r][h0+0] = (v0.x - mu) * inv * sc[h0+0] + bi[h0+0];
        sm[r][h0+1] = (v0.y - mu) * inv * sc[h0+1] + bi[h0+1];
        sm[r][h0+2] = (v0.z - mu) * inv * sc[h0+2] + bi[h0+2];
        sm[r][h0+3] = (v0.w - mu) * inv * sc[h0+3] + bi[h0+3];
        sm[r][h1+0] = (v1.x - mu) * inv * sc[h1+0] + bi[h1+0];
        sm[r][h1+1] = (v1.y - mu) * inv * sc[h1+1] + bi[h1+1];
        sm[r][h1+2] = (v1.z - mu) * inv * sc[h1+2] + bi[h1+2];
        sm[r][h1+3] = (v1.w - mu) * inv * sc[h1+3] + bi[h1+3];
    }
    __syncthreads();

    int b  = m0 >> 11;
    int l0 = m0 & 2047;
    for (int h = warp; h < HH; h += 8) {
        g_zt[((size_t)(b * HH + h)) * LL + l0 + lane] = sm[lane][h];
    }
}

// ------------------------------------------------------------------
// S4D discretization + dA^CLEN
// ------------------------------------------------------------------
__global__ void ssm_params_kernel(const float* __restrict__ lre,
                                  const float* __restrict__ lim,
                                  const float* __restrict__ cre,
                                  const float* __restrict__ cim,
                                  const float* __restrict__ lstep) {
    int idx = blockIdx.x * blockDim.x + threadIdx.x;
    if (idx >= HH * NN) return;
    int h = idx >> 6;
    float Lre = lre[idx], Lim = lim[idx];
    float Cre = cre[idx], Cim = cim[idx];
    float dt  = expf(lstep[h]);
    float mag = expf(Lre * dt);
    float th  = Lim * dt;
    float dar = mag * cosf(th);
    float dai = mag * sinf(th);
    float den = Lre * Lre + Lim * Lim;
    float nr = dar - 1.0f, ni = dai;
    float dbr = (nr * Lre + ni * Lim) / den;
    float dbi = (ni * Lre - nr * Lim) / den;
    float wr = Cre * dbr - Cim * dbi;
    float wi = Cre * dbi + Cim * dbr;
    g_ar[idx]  = dar;
    g_ai[idx]  = dai;
    g_wr[idx]  = 2.0f * wr;
    g_win[idx] = -2.0f * wi;
    double dtd = exp((double)lstep[h]);
    double mr  = exp((double)Lre * dtd * (double)CLEN);
    double thd = (double)Lim * dtd * (double)CLEN;
    g_apr[idx] = (float)(mr * cos(thd));
    g_api[idx] = (float)(mr * sin(thd));
}

// ------------------------------------------------------------------
// Scan pass 1 (fuses gelu for chunk 0)
// ------------------------------------------------------------------
__global__ void __launch_bounds__(256, 4) scan1_kernel(const float* __restrict__ dcoef) {
    int warp = (blockIdx.x * blockDim.x + threadIdx.x) >> 5;
    int lane = threadIdx.x & 31;
    int half = lane >> 4;
    int ln   = lane & 15;
    int unit = warp * 2 + half;
    int seq  = unit >> 2;
    int c    = unit & (CH - 1);
    int h = seq & 255;
    int base = h * NN + ln * 4;

    float a0r = g_ar[base+0], a1r = g_ar[base+1], a2r = g_ar[base+2], a3r = g_ar[base+3];
    float a0i = g_ai[base+0], a1i = g_ai[base+1], a2i = g_ai[base+2], a3i = g_ai[base+3];
    float w0r = g_wr[base+0], w1r = g_wr[base+1], w2r = g_wr[base+2], w3r = g_wr[base+3];
    float w0n = g_win[base+0], w1n = g_win[base+1], w2n = g_win[base+2], w3n = g_win[base+3];

    ull ar01 = pk2(a0r, a1r), ar23 = pk2(a2r, a3r);
    ull ai01 = pk2(a0i, a1i), ai23 = pk2(a2i, a3i);
    ull an01 = pk2(-a0i, -a1i), an23 = pk2(-a2i, -a3i);
    ull wr01 = pk2(w0r, w1r), wr23 = pk2(w2r, w3r);
    ull wn01 = pk2(w0n, w1n), wn23 = pk2(w2n, w3n);

    ull sr01 = 0ULL, si01 = 0ULL, sr23 = 0ULL, si23 = 0ULL;

    const float* zp = g_zt + (size_t)seq * LL + (size_t)c * CLEN;
    float*       yp = g_yt + (size_t)seq * LL + (size_t)c * CLEN;
    float dv = dcoef[h];
    bool first = (c == 0);

    for (int l0 = 0; l0 < CLEN; l0 += 16) {
        float zv = zp[l0 + ln];
        float c16[16];
        #pragma unroll
        for (int t = 0; t < 16; ++t) {
            float zb = __shfl_sync(0xffffffffu, zv, t, 16);
            ull z2 = pk2(zb, zb);
            ull t0 = fma2(an01, si01, z2);
            si01   = fma2(ai01, sr01, mul2(ar01, si01));
            sr01   = fma2(ar01, sr01, t0);
            ull t1 = fma2(an23, si23, z2);
            si23   = fma2(ai23, sr23, mul2(ar23, si23));
            sr23   = fma2(ar23, sr23, t1);
            ull av = fma2(wr01, sr01, mul2(wn01, si01));
            av = fma2(wr23, sr23, av);
            av = fma2(wn23, si23, av);
            float alo, ahi;
            upk2(av, alo, ahi);
            c16[t] = alo + ahi;
        }
        #pragma unroll
        for (int off = 8; off >= 1; off >>= 1) {
            bool up = (ln & off) != 0;
            #pragma unroll
            for (int j = 0; j < off; ++j) {
                float send = up ? c16[j] : c16[j + off];
                float keep = up ? c16[j + off] : c16[j];
                c16[j] = keep + __shfl_xor_sync(0xffffffffu, send, off, 16);
            }
        }
        float yv = fmaf(dv, zv, c16[0]);
        if (first) yv = gelu1(yv);
        yp[l0 + ln] = yv;
    }

    float4 vr, vi;
    upk2(sr01, vr.x, vr.y); upk2(sr23, vr.z, vr.w);
    upk2(si01, vi.x, vi.y); upk2(si23, vi.z, vi.w);
    size_t so = (size_t)unit * NN + ln * 4;
    *reinterpret_cast<float4*>(&g_esr[so]) = vr;
    *reinterpret_cast<float4*>(&g_esi[so]) = vi;
}

// ------------------------------------------------------------------
// Combine
// ------------------------------------------------------------------
__global__ void combine_kernel() {
    int t = blockIdx.x * blockDim.x + threadIdx.x;
    int seq = t >> 6;
    int n   = t & 63;
    int h   = seq & 255;
    float apr = g_apr[h * NN + n];
    float api = g_api[h * NN + n];
    float sr = 0.0f, si = 0.0f;
    #pragma unroll
    for (int c = 0; c < CH - 1; ++c) {
        size_t eo = (size_t)(seq * CH + c) * NN + n;
        float er = g_esr[eo], ei = g_esi[eo];
        float nsr = apr * sr - api * si + er;
        float nsi = apr * si + api * sr + ei;
        sr = nsr; si = nsi;
        size_t io = (size_t)(seq * CH + c + 1) * NN + n;
        g_isr[io] = sr;
        g_isi[io] = si;
    }
}

// ------------------------------------------------------------------
// Scan pass 2 (adds correction, then fused gelu)
// ------------------------------------------------------------------
__global__ void __launch_bounds__(256, 4) scan2_kernel() {
    int warp = (blockIdx.x * blockDim.x + threadIdx.x) >> 5;
    int lane = threadIdx.x & 31;
    int half = lane >> 4;
    int ln   = lane & 15;
    int unit = warp * 2 + half;
    int seq  = unit / (CH - 1);
    int c    = unit - seq * (CH - 1) + 1;
    int h = seq & 255;
    int base = h * NN + ln * 4;

    float a0r = g_ar[base+0], a1r = g_ar[base+1], a2r = g_ar[base+2], a3r = g_ar[base+3];
    float a0i = g_ai[base+0], a1i = g_ai[base+1], a2i = g_ai[base+2], a3i = g_ai[base+3];
    float w0r = g_wr[base+0], w1r = g_wr[base+1], w2r = g_wr[base+2], w3r = g_wr[base+3];
    float w0n = g_win[base+0], w1n = g_win[base+1], w2n = g_win[base+2], w3n = g_win[base+3];

    ull ar01 = pk2(a0r, a1r), ar23 = pk2(a2r, a3r);
    ull ai01 = pk2(a0i, a1i), ai23 = pk2(a2i, a3i);
    ull an01 = pk2(-a0i, -a1i), an23 = pk2(-a2i, -a3i);

    size_t io = (size_t)(seq * CH + c) * NN + ln * 4;
    float4 s_r = *reinterpret_cast<const float4*>(&g_isr[io]);
    float4 s_i = *reinterpret_cast<const float4*>(&g_isi[io]);
    ull sr01 = pk2(s_r.x, s_r.y), sr23 = pk2(s_r.z, s_r.w);
    ull si01 = pk2(s_i.x, s_i.y), si23 = pk2(s_i.z, s_i.w);

    ull tr01 = fma2(ar01, sr01, mul2(an01, si01));
    ull ti01 = fma2(ai01, sr01, mul2(ar01, si01));
    ull tr23 = fma2(ar23, sr23, mul2(an23, si23));
    ull ti23 = fma2(ai23, sr23, mul2(ar23, si23));

    ull wr01 = pk2(w0r, w1r), wr23 = pk2(w2r, w3r);
    ull wn01 = pk2(w0n, w1n), wn23 = pk2(w2n, w3n);
    ull wm01 = pk2(-w0n, -w1n), wm23 = pk2(-w2n, -w3n);
    ull ur01 = fma2(wr01, tr01, mul2(wn01, ti01));
    ull ui01 = fma2(wr01, ti01, mul2(wm01, tr01));
    ull ur23 = fma2(wr23, tr23, mul2(wn23, ti23));
    ull ui23 = fma2(wr23, ti23, mul2(wm23, tr23));

    float* yp = g_yt + (size_t)seq * LL + (size_t)c * CLEN;

    for (int l0 = 0; l0 < CLEN; l0 += 16) {
        float c16[16];
        #pragma unroll
        for (int t = 0; t < 16; ++t) {
            ull sm = add2(ur01, ur23);
            float alo, ahi;
            upk2(sm, alo, ahi);
            c16[t] = alo + ahi;
            ull m0 = mul2(an01, ui01);
            ui01 = fma2(ai01, ur01, mul2(ar01, ui01));
            ur01 = fma2(ar01, ur01, m0);
            ull m1 = mul2(an23, ui23);
            ui23 = fma2(ai23, ur23, mul2(ar23, ui23));
            ur23 = fma2(ar23, ur23, m1);
        }
        #pragma unroll
        for (int off = 8; off >= 1; off >>= 1) {
            bool up = (ln & off) != 0;
            #pragma unroll
            for (int j = 0; j < off; ++j) {
                float send = up ? c16[j] : c16[j + off];
                float keep = up ? c16[j + off] : c16[j];
                c16[j] = keep + __shfl_xor_sync(0xffffffffu, send, off, 16);
            }
        }
        float yv = yp[l0 + ln] + c16[0];
        yp[l0 + ln] = gelu1(yv);
    }
}

// ------------------------------------------------------------------
// GLU GEMM via mma.sync tf32 (m16n8k8).
//   D1[m][n] = sum_k Y[m][k] * W1[n][k]   (+ D2 with W2)
//   h[m][n] += (D1 + b1[n]) * sigmoid(D2 + b2[n])
// CTA: 128 m x 64 n, 8 warps (4 along m x 2 along n), 32x32 per warp.
// K staged in chunks of 32. A staged directly from g_yt ([k][m]).
// ------------------------------------------------------------------
#define ASTR 136
#define BSTR 72
__global__ void __launch_bounds__(256) glu_gemm_mma(
        const float* __restrict__ W1, const float* __restrict__ W2,
        const float* __restrict__ b1, const float* __restrict__ b2) {
    __shared__ uint32_t As [32 * ASTR];   // [k][m], tf32
    __shared__ uint32_t Bs1[32 * BSTR];   // [k][n], tf32
    __shared__ uint32_t Bs2[32 * BSTR];

    int tid  = threadIdx.x;
    int wid  = tid >> 5;
    int lane = tid & 31;
    int g    = lane >> 2;      // groupID 0..7
    int t    = lane & 3;       // threadID_in_group 0..3
    int wm   = wid & 3;        // warp m quarter (32 rows)
    int wn   = wid >> 2;       // warp n half (32 cols)

    int m0  = blockIdx.x * 128;
    int n0  = blockIdx.y * 64;
    int bch = m0 >> 11;        // batch index
    int ml0 = m0 & 2047;       // l offset within batch

    float acc1[2][4][4];       // [mi][nj][reg]
    float acc2[2][4][4];
    #pragma unroll
    for (int mi = 0; mi < 2; ++mi)
        #pragma unroll
        for (int nj = 0; nj < 4; ++nj)
            #pragma unroll
            for (int r = 0; r < 4; ++r) { acc1[mi][nj][r] = 0.f; acc2[mi][nj][r] = 0.f; }

    for (int kc = 0; kc < HH; kc += 32) {
        __syncthreads();
        // stage A: 32 k-rows x 128 m, direct from g_yt (coalesced)
        #pragma unroll
        for (int it = 0; it < 4; ++it) {
            int item = it * 256 + tid;          // 0..1023
            int krow = item >> 5;               // 0..31
            int c4   = (item & 31) * 4;         // m quad
            const float* src = &g_yt[(size_t)(bch * HH + kc + krow) * LL + ml0 + c4];
            float4 v = *reinterpret_cast<const float4*>(src);
            uint32_t* dst = &As[krow * ASTR + c4];
            asm volatile("st.shared.v4.b32 [%0], {%1,%2,%3,%4};"
                :: "l"(dst), "r"(f2tf32(v.x)), "r"(f2tf32(v.y)),
                   "r"(f2tf32(v.z)), "r"(f2tf32(v.w)) : "memory");
        }
        // stage B1/B2: [k][n] from W[n][k] (transpose in smem write).
        // item: gg = item & 63 (n), kq = item >> 6 (k quad)
        #pragma unroll
        for (int it = 0; it < 2; ++it) {
            int item = it * 256 + tid;          // 0..511
            int gg = item & 63;
            int kq = item >> 6;                 // 0..7
            size_t off = (size_t)(n0 + gg) * HH + kc + kq * 4;
            float4 w1 = *reinterpret_cast<const float4*>(&W1[off]);
            float4 w2 = *reinterpret_cast<const float4*>(&W2[off]);
            int kb = kq * 4;
            Bs1[(kb+0) * BSTR + gg] = f2tf32(w1.x);
            Bs1[(kb+1) * BSTR + gg] = f2tf32(w1.y);
            Bs1[(kb+2) * BSTR + gg] = f2tf32(w1.z);
            Bs1[(kb+3) * BSTR + gg] = f2tf32(w1.w);
            Bs2[(kb+0) * BSTR + gg] = f2tf32(w2.x);
            Bs2[(kb+1) * BSTR + gg] = f2tf32(w2.y);
            Bs2[(kb+2) * BSTR + gg] = f2tf32(w2.z);
            Bs2[(kb+3) * BSTR + gg] = f2tf32(w2.w);
        }
        __syncthreads();

        #pragma unroll
        for (int ks = 0; ks < 4; ++ks) {
            int kb = ks * 8;
            // A fragments for 2 m-tiles
            uint32_t af[2][4];
            #pragma unroll
            for (int mi = 0; mi < 2; ++mi) {
                int mrow = wm * 32 + mi * 16;
                af[mi][0] = As[(kb + t)     * ASTR + mrow + g];
                af[mi][1] = As[(kb + t)     * ASTR + mrow + g + 8];
                af[mi][2] = As[(kb + t + 4) * ASTR + mrow + g];
                af[mi][3] = As[(kb + t + 4) * ASTR + mrow + g + 8];
            }
            #pragma unroll
            for (int nj = 0; nj < 4; ++nj) {
                int ncol = wn * 32 + nj * 8 + g;
                uint32_t bA0 = Bs1[(kb + t)     * BSTR + ncol];
                uint32_t bA1 = Bs1[(kb + t + 4) * BSTR + ncol];
                uint32_t bB0 = Bs2[(kb + t)     * BSTR + ncol];
                uint32_t bB1 = Bs2[(kb + t + 4) * BSTR + ncol];
                #pragma unroll
                for (int mi = 0; mi < 2; ++mi) {
                    mma_tf32(acc1[mi][nj], af[mi][0], af[mi][1], af[mi][2], af[mi][3], bA0, bA1);
                    mma_tf32(acc2[mi][nj], af[mi][0], af[mi][1], af[mi][2], af[mi][3], bB0, bB1);
                }
            }
        }
    }

    // epilogue: c0 -> (row g, col 2t), c1 -> (g, 2t+1), c2 -> (g+8, 2t), c3 -> (g+8, 2t+1)
    #pragma unroll
    for (int nj = 0; nj < 4; ++nj) {
        int ncol = n0 + wn * 32 + nj * 8 + t * 2;
        float bb1a = b1[ncol], bb1b = b1[ncol + 1];
        float bb2a = b2[ncol], bb2b = b2[ncol + 1];
        #pragma unroll
        for (int mi = 0; mi < 2; ++mi) {
            #pragma unroll
            for (int rr = 0; rr < 2; ++rr) {
                int mrow = m0 + wm * 32 + mi * 16 + g + rr * 8;
                float* hp = &g_h[(size_t)mrow * HH + ncol];
                float2 hv = *reinterpret_cast<float2*>(hp);
                float d1a = acc1[mi][nj][rr * 2 + 0] + bb1a;
                float d1b = acc1[mi][nj][rr * 2 + 1] + bb1b;
                float d2a = acc2[mi][nj][rr * 2 + 0] + bb2a;
                float d2b = acc2[mi][nj][rr * 2 + 1] + bb2b;
                hv.x += d1a * (1.0f / (1.0f + expf(-d2a)));
                hv.y += d1b * (1.0f / (1.0f + expf(-d2b)));
                *reinterpret_cast<float2*>(hp) = hv;
            }
        }
    }
}

// ------------------------------------------------------------------
// Decoder
// ------------------------------------------------------------------
__global__ void dec_kernel(const float* __restrict__ dw,
                           const float* __restrict__ db,
                           float* __restrict__ out) {
    int warp = (blockIdx.x * blockDim.x + threadIdx.x) >> 5;
    int lane = threadIdx.x & 31;
    const float* row = g_h + (size_t)warp * HH;
    float hr[8];
    #pragma unroll
    for (int k = 0; k < 8; ++k) hr[k] = row[lane + 32 * k];
    for (int o = 0; o < OUTD; ++o) {
        const float* wrow = dw + o * HH + lane;
        float acc = 0.0f;
        #pragma unroll
        for (int k = 0; k < 8; ++k) acc = fmaf(hr[k], wrow[32 * k], acc);
        #pragma unroll
        for (int m = 16; m; m >>= 1) acc += __shfl_xor_sync(0xffffffffu, acc, m);
        if (lane == 0) out[(size_t)warp * OUTD + o] = acc + db[o];
    }
}

// ------------------------------------------------------------------
extern "C" void kernel_launch(void* const* d_in, const int* in_sizes, int n_in,
                              void* d_out, int out_size) {
    const float* x     = (const float*)d_in[0];
    const float* enc_w = (const float*)d_in[1];
    const float* enc_b = (const float*)d_in[2];
    const float* lre   = (const float*)d_in[3];
    const float* lim   = (const float*)d_in[4];
    const float* cre   = (const float*)d_in[5];
    const float* cim   = (const float*)d_in[6];
    const float* dd    = (const float*)d_in[7];
    const float* lstep = (const float*)d_in[8];
    const float* lns   = (const float*)d_in[9];
    const float* lnb   = (const float*)d_in[10];
    const float* ow    = (const float*)d_in[11];
    const float* ob    = (const float*)d_in[12];
    const float* o2w   = (const float*)d_in[13];
    const float* o2b   = (const float*)d_in[14];
    const float* dw    = (const float*)d_in[15];
    const float* db    = (const float*)d_in[16];
    float* out = (float*)d_out;

    enc_kernel<<<(BB * LL) / 16, 256>>>(x, enc_w, enc_b);

    for (int li = 0; li < NLAY; ++li) {
        ln_kernel<<<(BB * LL) / 32, 256>>>(lns + li * HH, lnb + li * HH);
        ssm_params_kernel<<<(HH * NN) / 256, 256>>>(
            lre + li * HH * NN, lim + li * HH * NN,
            cre + li * HH * NN, cim + li * HH * NN, lstep + li * HH);
        scan1_kernel<<<(BB * HH * CH) / 16, 256>>>(dd + li * HH);
        combine_kernel<<<(BB * HH * NN) / 256, 256>>>();
        scan2_kernel<<<(BB * HH * (CH - 1)) / 16, 256>>>();
        glu_gemm_mma<<<dim3((BB * LL) / 128, HH / 64), 256>>>(
            ow + li * HH * HH, o2w + li * HH * HH,
            ob + li * HH, o2b + li * HH);
    }

    dec_kernel<<<(BB * LL) / 8, 256>>>(dw, db, out);
}